// round 15
// baseline (speedup 1.0000x reference)
#include <cuda_runtime.h>

// CANN recurrent net — single persistent kernel, minimal flag-barrier grid sync.
//   step t: y = J @ s_{t-1};  U = y/recSum_{t-1} + Iext;  s_t = (0.2 U)^2
//   outputs: U_14 (1680), recSum_14 (1), r_14 = s_14/recSum_14 (1680)
//
// 148 CTAs x 384 thr (single wave, 1 CTA/SM), 1 warp = 1 row, J register-resident
// for the WHOLE run (loaded once). Per-iteration grid barrier:
//   publish rows (st.cg) -> bar -> tid0: atom.release.add counter;
//   last arrival st.release's g_flag[t] = run+1; every CTA's tid0 alone spins
//   ld.acquire on that one line (other warps parked at bar.sync -> no issue
//   pressure, no L2 scan traffic). Counters/flags monotonic -> replay-safe.

#define Nn     1680
#define NBLK   148
#define TPB    384          // 12 warps
#define ITERS  14
#define KC     0.005f

__device__ float    g_s[2][Nn];          // unnormalized s vectors, parity-buffered
__device__ unsigned g_cnt[ITERS + 1];    // per-step arrival counters (monotonic)
__device__ unsigned g_flag[ITERS + 1];   // per-step completion flags  (monotonic)
__device__ unsigned g_run;               // replay counter

__device__ __forceinline__ float4 ldcg4(const float4* p) {
    float4 v;
    asm volatile("ld.global.cg.v4.f32 {%0,%1,%2,%3}, [%4];"
                 : "=f"(v.x), "=f"(v.y), "=f"(v.z), "=f"(v.w) : "l"(p));
    return v;
}
__device__ __forceinline__ void stcg(float* p, float v) {
    asm volatile("st.global.cg.f32 [%0], %1;" :: "l"(p), "f"(v) : "memory");
}
__device__ __forceinline__ unsigned atom_add_release(unsigned* p, unsigned v) {
    unsigned old;
    asm volatile("atom.release.gpu.global.add.u32 %0, [%1], %2;"
                 : "=r"(old) : "l"(p), "r"(v) : "memory");
    return old;
}
__device__ __forceinline__ unsigned ld_acquire(const unsigned* p) {
    unsigned v;
    asm volatile("ld.acquire.gpu.global.u32 %0, [%1];" : "=r"(v) : "l"(p) : "memory");
    return v;
}
__device__ __forceinline__ void st_release(unsigned* p, unsigned v) {
    asm volatile("st.release.gpu.global.u32 [%0], %1;" :: "l"(p), "r"(v) : "memory");
}

__global__ void __launch_bounds__(TPB, 1)
cann_kernel(const float* __restrict__ net_in,
            const float* __restrict__ J,
            float* __restrict__ out)
{
    __shared__ __align__(16) float s_sm[Nn];
    __shared__ float s_part[12];
    __shared__ unsigned s_run;

    const int tid  = threadIdx.x;
    const int lane = tid & 31;
    const int wid  = tid >> 5;
    const int bid  = blockIdx.x;
    const int row  = wid * NBLK + bid;          // 12*148 = 1776 >= 1680
    const bool active = (row < Nn);

    // Replay id: 148 increments per run; /NBLK is uniform across the run's CTAs
    // (runs are stream-serialized). Monotonic -> no reset needed.
    if (tid == 0) s_run = atomicAdd(&g_run, 1u) / NBLK;

    // ---- J row -> registers once for the whole run (1680 = 13*128 + 16) ----
    float4 Jr[13];
    float jtail = 0.f, iext = 0.f;
    if (active) {
        iext = __ldg(&net_in[row]);
        const float* Jrow = J + (size_t)row * Nn;
        const float4* Jp = reinterpret_cast<const float4*>(Jrow);
        #pragma unroll
        for (int j = 0; j < 13; ++j) Jr[j] = __ldg(&Jp[j * 32 + lane]);
        if (lane < 16) jtail = __ldg(&Jrow[1664 + lane]);
    }

    // ---- stage s_0 = r0 ----
    {
        const float4* r4 = reinterpret_cast<const float4*>(net_in + Nn);
        #pragma unroll
        for (int k = 0; k < 2; ++k) {
            int i = tid + k * TPB;
            if (i < Nn / 4) reinterpret_cast<float4*>(s_sm)[i] = __ldg(&r4[i]);
        }
    }
    __syncthreads();
    const unsigned run = s_run;
    const unsigned tag = run + 1u;

    for (int t = 1; t <= ITERS; ++t) {
        // ---- matvec (register J row x smem s_{t-1}) with fused recSum ----
        if (active) {
            const float4* s4 = reinterpret_cast<const float4*>(s_sm);
            float a0 = 0.f, a1 = 0.f, rs = 0.f;
            #pragma unroll
            for (int j = 0; j < 13; ++j) {
                float4 b = s4[j * 32 + lane];
                rs += (b.x + b.y) + (b.z + b.w);
                if (j & 1) {
                    a1 = fmaf(Jr[j].x, b.x, a1); a1 = fmaf(Jr[j].y, b.y, a1);
                    a1 = fmaf(Jr[j].z, b.z, a1); a1 = fmaf(Jr[j].w, b.w, a1);
                } else {
                    a0 = fmaf(Jr[j].x, b.x, a0); a0 = fmaf(Jr[j].y, b.y, a0);
                    a0 = fmaf(Jr[j].z, b.z, a0); a0 = fmaf(Jr[j].w, b.w, a0);
                }
            }
            if (lane < 16) {
                float bt = s_sm[1664 + lane];
                rs += bt;
                a1 = fmaf(jtail, bt, a1);
            }
            float acc = a0 + a1;
            #pragma unroll
            for (int o = 16; o; o >>= 1) {
                acc += __shfl_xor_sync(0xffffffffu, acc, o);
                rs  += __shfl_xor_sync(0xffffffffu, rs,  o);
            }
            if (lane == 0) {
                const float invDen = (t == 1) ? 1.0f : 1.0f / (KC * rs);
                float U  = fmaf(acc, invDen, iext);
                float u2 = 0.2f * U;
                float sv = u2 * u2;
                stcg(&g_s[t & 1][row], sv);
                if (t == ITERS) out[row] = U;        // U_14
            }
        }

        // ---- grid barrier: arrive (release) + single-line flag + 1-thread spin
        __syncthreads();   // all 12 rows of this CTA published (block-perform)
        if (tid == 0) {
            unsigned old = atom_add_release(&g_cnt[t], 1u);
            if (old == run * NBLK + (NBLK - 1u)) {
                st_release(&g_flag[t], tag);         // last arrival opens the gate
            } else {
                while ((int)(ld_acquire(&g_flag[t]) - tag) < 0) { /* spin */ }
            }
        }
        __syncthreads();   // 11 warps were parked here, zero issue pressure

        // ---- stage s_t for the next iteration ----
        if (t < ITERS) {
            const float4* sp = reinterpret_cast<const float4*>(g_s[t & 1]);
            #pragma unroll
            for (int k = 0; k < 2; ++k) {
                int i = tid + k * TPB;
                if (i < Nn / 4) reinterpret_cast<float4*>(s_sm)[i] = ldcg4(&sp[i]);
            }
            __syncthreads();
        }
    }

    // ---- epilogue (CTA 0 only): recSum_14, r_14 ----
    if (bid == 0) {
        const float4* sp = reinterpret_cast<const float4*>(g_s[ITERS & 1]);
        float4 a = make_float4(0.f, 0.f, 0.f, 0.f);
        float4 b = make_float4(0.f, 0.f, 0.f, 0.f);
        a = ldcg4(&sp[tid]);                          // tid < 384 < 420
        const bool has2 = (tid + TPB) < Nn / 4;       // tid < 36
        if (has2) b = ldcg4(&sp[tid + TPB]);
        float v = ((a.x + a.y) + (a.z + a.w)) + ((b.x + b.y) + (b.z + b.w));
        #pragma unroll
        for (int o = 16; o; o >>= 1) v += __shfl_xor_sync(0xffffffffu, v, o);
        if (lane == 0) s_part[wid] = v;
        __syncthreads();
        float rsum = 0.f;
        #pragma unroll
        for (int w = 0; w < 12; ++w) rsum += s_part[w];
        const float recS = KC * rsum;

        if (tid == 0) out[Nn] = recS;                 // recSum_14
        float* r14 = out + Nn + 1;                    // r_14
        r14[4 * tid + 0] = a.x / recS;
        r14[4 * tid + 1] = a.y / recS;
        r14[4 * tid + 2] = a.z / recS;
        r14[4 * tid + 3] = a.w / recS;
        if (has2) {
            r14[4 * (tid + TPB) + 0] = b.x / recS;
            r14[4 * (tid + TPB) + 1] = b.y / recS;
            r14[4 * (tid + TPB) + 2] = b.z / recS;
            r14[4 * (tid + TPB) + 3] = b.w / recS;
        }
    }
}

extern "C" void kernel_launch(void* const* d_in, const int* in_sizes, int n_in,
                              void* d_out, int out_size)
{
    const float* a = (const float*)d_in[0];
    const float* b = (const float*)d_in[1];
    const float* net_in = a;
    const float* J      = b;
    if (n_in >= 2 && in_sizes[0] > in_sizes[1]) { net_in = b; J = a; }
    cann_kernel<<<NBLK, TPB>>>(net_in, J, (float*)d_out);
}